// round 3
// baseline (speedup 1.0000x reference)
#include <cuda_runtime.h>
#include <math.h>

#define BSZ   16
#define GR    52
#define HH    256
#define WW    256
#define HW    (HH * WW)
#define NT    512
#define NW    (NT / 32)
#define ITERS (HW / (NT * 4))   // 32 float4 iters per thread
#define GRP   8                 // prefetch depth
#define NGRP  (ITERS / GRP)     // 4 groups

__global__ __launch_bounds__(NT, 2)
void prm_kernel(const float* __restrict__ x,
                const float* __restrict__ wgt,
                const float* __restrict__ bias,
                const float* __restrict__ one,
                const float* __restrict__ zero,
                const float* __restrict__ theta,
                const float* __restrict__ scale,
                float* __restrict__ out)
{
    const int p    = blockIdx.x;           // plane = b*GR + g
    const int g    = p % GR;
    const int tid  = threadIdx.x;
    const int lane = tid & 31;
    const int wid  = tid >> 5;

    const float4* x4 = (const float4*)x + (size_t)p * (HW / 4);
    float4*       o4 = (float4*)out     + (size_t)p * (HW / 4);

    __shared__ __align__(16) float grow[HH];
    __shared__ __align__(16) float gcol[WW];
    __shared__ float r0[NW], r1[NW], r2[NW];
    __shared__ int   ri[NW];
    __shared__ float bc[8];

    // ================= Pass 1: argmax (first occurrence), sum, sumsq ==========
    float bv = -3.402823466e38f;
    int   bi = 0x7fffffff;
    float s0 = 0.f, s1 = 0.f, q0 = 0.f, q1 = 0.f;

    #pragma unroll
    for (int grp = 0; grp < NGRP; ++grp) {
        float4 v[GRP];
        #pragma unroll
        for (int j = 0; j < GRP; ++j)
            v[j] = x4[(grp * GRP + j) * NT + tid];
        #pragma unroll
        for (int j = 0; j < GRP; ++j) {
            float4 t = v[j];
            int i0 = ((grp * GRP + j) * NT + tid) << 2;
            s0 += t.x + t.y;            s1 += t.z + t.w;
            q0 += t.x * t.x + t.y * t.y; q1 += t.z * t.z + t.w * t.w;
            float m = fmaxf(fmaxf(t.x, t.y), fmaxf(t.z, t.w));
            if (m > bv) {   // first-occurrence: x before y before z before w
                bv = m;
                bi = i0 + (t.x == m ? 0 : (t.y == m ? 1 : (t.z == m ? 2 : 3)));
            }
        }
    }
    float s = s0 + s1, s2 = q0 + q1;

    #pragma unroll
    for (int o = 16; o; o >>= 1) {
        s  += __shfl_down_sync(0xffffffffu, s,  o);
        s2 += __shfl_down_sync(0xffffffffu, s2, o);
        float ov = __shfl_down_sync(0xffffffffu, bv, o);
        int   oi = __shfl_down_sync(0xffffffffu, bi, o);
        if (ov > bv || (ov == bv && oi < bi)) { bv = ov; bi = oi; }
    }
    if (lane == 0) { r0[wid] = s; r1[wid] = s2; r2[wid] = bv; ri[wid] = bi; }
    __syncthreads();

    if (wid == 0) {
        s  = (lane < NW) ? r0[lane] : 0.f;
        s2 = (lane < NW) ? r1[lane] : 0.f;
        bv = (lane < NW) ? r2[lane] : -3.402823466e38f;
        bi = (lane < NW) ? ri[lane] : 0x7fffffff;
        #pragma unroll
        for (int o = 16; o; o >>= 1) {
            s  += __shfl_down_sync(0xffffffffu, s,  o);
            s2 += __shfl_down_sync(0xffffffffu, s2, o);
            float ov = __shfl_down_sync(0xffffffffu, bv, o);
            int   oi = __shfl_down_sync(0xffffffffu, bi, o);
            if (ov > bv || (ov == bv && oi < bi)) { bv = ov; bi = oi; }
        }
        if (lane == 0) {
            bc[0] = (float)(bi >> 8);                 // qrow
            bc[1] = (float)(bi & 255);                // qcol
            bc[2] = bv * zero[g];                     // A
            bc[3] = s * (1.0f / (float)HW) * one[g];  // B
            bc[4] = s;                                // Sx
            bc[5] = s2;                               // Sx2
        }
    }
    __syncthreads();

    // ============ Gaussian LUTs pre-scaled by 0.5*A (e = A*dist) ==============
    {
        float sigma  = scale[0];
        float ln     = -logf(sigma) - 0.91893853320467274f;
        float inv2s2 = 0.5f / (sigma * sigma);
        float hA     = 0.5f * bc[2];
        if (tid < HH) {
            float d = fabsf((float)tid - bc[0]) * theta[0];
            grow[tid] = hA * __expf(ln - d * d * inv2s2);
        } else {
            int   c = tid - HH;
            float d = fabsf((float)c - bc[1]) * theta[1];
            gcol[c] = hA * __expf(ln - d * d * inv2s2);
        }
    }
    __syncthreads();

    // ============ Pass 2: Σ x·e, Σ x²·e, Σ x²·e² ==============================
    // gcol index is iteration-invariant: hoist the LDS.128 out of the loop.
    float4 gc = *(const float4*)&gcol[(4 * tid) & 255];
    const int rbase = tid >> 6;   // grow row = 8*it + rbase

    float sxe = 0.f, sx2e = 0.f, sx2e2 = 0.f;
    #pragma unroll
    for (int grp = 0; grp < NGRP; ++grp) {
        float4 v[GRP];
        float  gr[GRP];
        #pragma unroll
        for (int j = 0; j < GRP; ++j) {
            int it = grp * GRP + j;
            v[j]  = x4[it * NT + tid];
            gr[j] = grow[8 * it + rbase];
        }
        #pragma unroll
        for (int j = 0; j < GRP; ++j) {
            float4 t = v[j];
            float e0 = gr[j] + gc.x, e1 = gr[j] + gc.y;
            float e2 = gr[j] + gc.z, e3 = gr[j] + gc.w;
            float a0 = t.x * e0, a1 = t.y * e1, a2 = t.z * e2, a3 = t.w * e3;
            sxe   += (a0 + a1) + (a2 + a3);
            float b0 = t.x * a0, b1 = t.y * a1, b2 = t.z * a2, b3 = t.w * a3;
            sx2e  += (b0 + b1) + (b2 + b3);
            sx2e2 += (b0 * e0 + b1 * e1) + (b2 * e2 + b3 * e3);
        }
    }
    #pragma unroll
    for (int o = 16; o; o >>= 1) {
        sxe   += __shfl_down_sync(0xffffffffu, sxe,   o);
        sx2e  += __shfl_down_sync(0xffffffffu, sx2e,  o);
        sx2e2 += __shfl_down_sync(0xffffffffu, sx2e2, o);
    }
    if (lane == 0) { r0[wid] = sxe; r1[wid] = sx2e; r2[wid] = sx2e2; }
    __syncthreads();

    if (wid == 0) {
        sxe   = (lane < NW) ? r0[lane] : 0.f;
        sx2e  = (lane < NW) ? r1[lane] : 0.f;
        sx2e2 = (lane < NW) ? r2[lane] : 0.f;
        #pragma unroll
        for (int o = 16; o; o >>= 1) {
            sxe   += __shfl_down_sync(0xffffffffu, sxe,   o);
            sx2e  += __shfl_down_sync(0xffffffffu, sx2e,  o);
            sx2e2 += __shfl_down_sync(0xffffffffu, sx2e2, o);
        }
        if (lane == 0) {
            float B     = bc[3];
            float Ssim  = sxe + B * bc[4];
            float Ssim2 = sx2e2 + 2.f * B * sx2e + B * B * bc[5];
            float mean  = Ssim * (1.0f / (float)HW);
            float var   = (Ssim2 - Ssim * Ssim * (1.0f / (float)HW)) * (1.0f / (float)(HW - 1));
            float sd    = sqrtf(fmaxf(var, 0.f)) + 1e-5f;
            float k1    = wgt[g] / sd;
            bc[6] = k1;
            bc[0] = B * k1;                 // Bk (folded into grow below)
            bc[1] = bias[g] - mean * k1;    // c0
        }
    }
    __syncthreads();

    // Fold k1 and Bk into LUTs: grow' = grow*k1 + Bk, gcol' = gcol*k1
    {
        float k1 = bc[6], Bk = bc[0];
        if (tid < HH) grow[tid] = fmaf(grow[tid], k1, Bk);
        else          gcol[tid - HH] *= k1;
    }
    __syncthreads();

    // ============ Pass 3: gated output ========================================
    {
        float c0 = bc[1];
        float4 gk = *(const float4*)&gcol[(4 * tid) & 255];
        #pragma unroll
        for (int grp = 0; grp < NGRP; ++grp) {
            float4 v[GRP];
            float  gr[GRP];
            #pragma unroll
            for (int j = 0; j < GRP; ++j) {
                int it = grp * GRP + j;
                v[j]  = __ldcs(&x4[it * NT + tid]);   // last use: evict-first
                gr[j] = grow[8 * it + rbase];
            }
            #pragma unroll
            for (int j = 0; j < GRP; ++j) {
                float4 t = v[j];
                float t0 = fmaf(t.x, gr[j] + gk.x, c0);
                float t1 = fmaf(t.y, gr[j] + gk.y, c0);
                float t2 = fmaf(t.z, gr[j] + gk.z, c0);
                float t3 = fmaf(t.w, gr[j] + gk.w, c0);
                float4 o;
                o.x = __fdividef(t.x, 1.f + __expf(-t0));
                o.y = __fdividef(t.y, 1.f + __expf(-t1));
                o.z = __fdividef(t.z, 1.f + __expf(-t2));
                o.w = __fdividef(t.w, 1.f + __expf(-t3));
                __stcs(&o4[(grp * GRP + j) * NT + tid], o);  // streaming store
            }
        }
    }
}

extern "C" void kernel_launch(void* const* d_in, const int* in_sizes, int n_in,
                              void* d_out, int out_size)
{
    const float* x     = (const float*)d_in[0];
    const float* wgt   = (const float*)d_in[1];
    const float* bias  = (const float*)d_in[2];
    const float* one   = (const float*)d_in[3];
    const float* zero  = (const float*)d_in[4];
    const float* theta = (const float*)d_in[5];
    const float* scale = (const float*)d_in[6];
    float* out = (float*)d_out;

    prm_kernel<<<BSZ * GR, NT>>>(x, wgt, bias, one, zero, theta, scale, out);
}

// round 7
// speedup vs baseline: 1.1644x; 1.1644x over previous
#include <cuda_runtime.h>
#include <cuda_bf16.h>
#include <math.h>

#define BSZ   16
#define GR    52
#define HH    256
#define WW    256
#define HW    (HH * WW)
#define NT    1024
#define NW    (NT / 32)          // 32 warps
#define ITERS (HW / (NT * 4))    // 16 float4 iters per thread
#define GRP   4
#define NGRP  (ITERS / GRP)      // 4
#define MBYTES (HW * 2)          // 131072 B of bf16 x^2

__global__ __launch_bounds__(NT, 1)
void prm_kernel(const float* __restrict__ x,
                const float* __restrict__ wgt,
                const float* __restrict__ bias,
                const float* __restrict__ one,
                const float* __restrict__ zero,
                const float* __restrict__ theta,
                const float* __restrict__ scale,
                float* __restrict__ out)
{
    extern __shared__ __align__(16) char Mraw[];   // 128 KB bf16 x^2 matrix
    __shared__ float rowx[HH];                     // signed row sums of x
    __shared__ float colx[WW];                     // signed col sums of x
    __shared__ __align__(16) float glut[HH];       // row gaussian / folded G
    __shared__ __align__(16) float hlut[WW];       // col gaussian / folded H
    __shared__ float red[6][NW];
    __shared__ float rv[NW]; __shared__ int rix[NW];
    __shared__ float bc[8];

    const int p    = blockIdx.x;          // plane = b*GR + g
    const int g    = p % GR;
    const int tid  = threadIdx.x;
    const int lane = tid & 31;
    const int wid  = tid >> 5;

    const float4* x4 = (const float4*)x + (size_t)p * (HW / 4);
    float4*       o4 = (float4*)out     + (size_t)p * (HW / 4);

    // zero marginals (atomically accumulated in pass 1)
    if (tid < HH)                rowx[tid] = 0.f;
    else if (tid < HH + WW)      colx[tid - HH] = 0.f;
    __syncthreads();

    // ================= Pass 1: the only DRAM read of x ========================
    // per thread, iteration it: row = 16*it + (tid>>6), cols 4*(tid&63)+{0..3}
    float bv = -3.402823466e38f;
    int   bi = 0x7fffffff;
    float s0 = 0.f, s1 = 0.f, q0a = 0.f, q1a = 0.f;
    float ca0 = 0.f, ca1 = 0.f, ca2 = 0.f, ca3 = 0.f;
    const int rsub = tid >> 6;            // row offset within the 16-row stripe
    const int csub = tid & 63;            // col group

    #pragma unroll
    for (int grp = 0; grp < NGRP; ++grp) {
        float4 v[GRP];
        #pragma unroll
        for (int j = 0; j < GRP; ++j)
            v[j] = x4[(grp * GRP + j) * NT + tid];
        #pragma unroll
        for (int j = 0; j < GRP; ++j) {
            int it = grp * GRP + j;
            float4 t = v[j];
            int i0 = ((it * NT + tid) << 2);
            float xx = t.x * t.x, yy = t.y * t.y, zz = t.z * t.z, ww = t.w * t.w;
            s0  += t.x + t.y;  s1  += t.z + t.w;
            q0a += xx + yy;    q1a += zz + ww;
            ca0 += t.x; ca1 += t.y; ca2 += t.z; ca3 += t.w;
            // store x^2 as bf16 into smem matrix
            __nv_bfloat162 p01 = __floats2bfloat162_rn(xx, yy);
            __nv_bfloat162 p23 = __floats2bfloat162_rn(zz, ww);
            uint2 pk = { *(unsigned*)&p01, *(unsigned*)&p23 };
            *(uint2*)(Mraw + 512 * (16 * it + rsub) + 8 * csub) = pk;
            // argmax (first occurrence)
            float m = fmaxf(fmaxf(t.x, t.y), fmaxf(t.z, t.w));
            if (m > bv) {
                bv = m;
                bi = i0 + (t.x == m ? 0 : (t.y == m ? 1 : (t.z == m ? 2 : 3)));
            }
            // row partial: one warp covers half a row
            float rp = (t.x + t.y) + (t.z + t.w);
            #pragma unroll
            for (int o = 16; o; o >>= 1) rp += __shfl_down_sync(0xffffffffu, rp, o);
            if (lane == 0) atomicAdd(&rowx[16 * it + (wid >> 1)], rp);
        }
    }
    // flush column accumulators (cols fixed per thread; 16 threads share a col)
    atomicAdd(&colx[4 * csub + 0], ca0);
    atomicAdd(&colx[4 * csub + 1], ca1);
    atomicAdd(&colx[4 * csub + 2], ca2);
    atomicAdd(&colx[4 * csub + 3], ca3);

    // block reduce sum / sumsq / argmax
    float s = s0 + s1, s2 = q0a + q1a;
    #pragma unroll
    for (int o = 16; o; o >>= 1) {
        s  += __shfl_down_sync(0xffffffffu, s,  o);
        s2 += __shfl_down_sync(0xffffffffu, s2, o);
        float ov = __shfl_down_sync(0xffffffffu, bv, o);
        int   oi = __shfl_down_sync(0xffffffffu, bi, o);
        if (ov > bv || (ov == bv && oi < bi)) { bv = ov; bi = oi; }
    }
    if (lane == 0) { red[0][wid] = s; red[1][wid] = s2; rv[wid] = bv; rix[wid] = bi; }
    __syncthreads();

    if (wid == 0) {
        s  = red[0][lane]; s2 = red[1][lane];
        bv = rv[lane];     bi = rix[lane];
        #pragma unroll
        for (int o = 16; o; o >>= 1) {
            s  += __shfl_down_sync(0xffffffffu, s,  o);
            s2 += __shfl_down_sync(0xffffffffu, s2, o);
            float ov = __shfl_down_sync(0xffffffffu, bv, o);
            int   oi = __shfl_down_sync(0xffffffffu, bi, o);
            if (ov > bv || (ov == bv && oi < bi)) { bv = ov; bi = oi; }
        }
        if (lane == 0) {
            bc[0] = (float)(bi >> 8);                  // qrow
            bc[1] = (float)(bi & 255);                 // qcol
            bc[2] = bv * zero[g];                      // A
            bc[3] = s * (1.0f / (float)HW) * one[g];   // B
            bc[4] = s;                                 // Sx
            bc[5] = s2;                                // Sx2
        }
    }
    __syncthreads();

    // ================= Gaussian LUTs (raw, unscaled) ==========================
    {
        float sigma  = scale[0];
        float ln     = -logf(sigma) - 0.91893853320467274f;
        float inv2s2 = 0.5f / (sigma * sigma);
        if (tid < HH) {
            float d = fabsf((float)tid - bc[0]) * theta[0];
            glut[tid] = __expf(ln - d * d * inv2s2);
        } else if (tid < HH + WW) {
            int   c = tid - HH;
            float d = fabsf((float)c - bc[1]) * theta[1];
            hlut[c] = __expf(ln - d * d * inv2s2);
        }
    }
    __syncthreads();

    // ===== smem sweep: LUT-weighted stats from bf16 x^2; T12 from marginals ===
    // warp w handles rows [8w, 8w+8); lane reads 8 bf16 (cols 8*lane..+7)
    float t3 = 0.f, t4 = 0.f, t5 = 0.f, t6 = 0.f, t7 = 0.f, t12 = 0.f;
    {
        float4 ha = *(const float4*)&hlut[8 * lane];
        float4 hb = *(const float4*)&hlut[8 * lane + 4];
        #pragma unroll
        for (int r8 = 0; r8 < 8; ++r8) {
            int r = 8 * wid + r8;
            uint4 mm = *(const uint4*)(Mraw + 512 * r + 16 * lane);
            float2 a0 = __bfloat1622float2(*(__nv_bfloat162*)&mm.x);
            float2 a1 = __bfloat1622float2(*(__nv_bfloat162*)&mm.y);
            float2 a2 = __bfloat1622float2(*(__nv_bfloat162*)&mm.z);
            float2 a3 = __bfloat1622float2(*(__nv_bfloat162*)&mm.w);
            float sm   = (a0.x + a0.y) + (a1.x + a1.y) + (a2.x + a2.y) + (a3.x + a3.y);
            float smh  = a0.x * ha.x + a0.y * ha.y + a1.x * ha.z + a1.y * ha.w
                       + a2.x * hb.x + a2.y * hb.y + a3.x * hb.z + a3.y * hb.w;
            float smh2 = a0.x * ha.x * ha.x + a0.y * ha.y * ha.y
                       + a1.x * ha.z * ha.z + a1.y * ha.w * ha.w
                       + a2.x * hb.x * hb.x + a2.y * hb.y * hb.y
                       + a3.x * hb.z * hb.z + a3.y * hb.w * hb.w;
            float gr = glut[r];
            t7 += gr * smh;        // Σ x² g h
            t4 += smh;             // Σ x² h
            t3 += gr * sm;         // Σ x² g
            t5 += gr * gr * sm;    // Σ x² g²
            t6 += smh2;            // Σ x² h²
        }
        if (tid < HH) t12 = glut[tid] * rowx[tid] + hlut[tid] * colx[tid];
    }
    #pragma unroll
    for (int o = 16; o; o >>= 1) {
        t3  += __shfl_down_sync(0xffffffffu, t3,  o);
        t4  += __shfl_down_sync(0xffffffffu, t4,  o);
        t5  += __shfl_down_sync(0xffffffffu, t5,  o);
        t6  += __shfl_down_sync(0xffffffffu, t6,  o);
        t7  += __shfl_down_sync(0xffffffffu, t7,  o);
        t12 += __shfl_down_sync(0xffffffffu, t12, o);
    }
    if (lane == 0) {
        red[0][wid] = t3; red[1][wid] = t4; red[2][wid] = t5;
        red[3][wid] = t6; red[4][wid] = t7; red[5][wid] = t12;
    }
    __syncthreads();

    if (wid == 0) {
        t3  = red[0][lane]; t4 = red[1][lane]; t5 = red[2][lane];
        t6  = red[3][lane]; t7 = red[4][lane]; t12 = red[5][lane];
        #pragma unroll
        for (int o = 16; o; o >>= 1) {
            t3  += __shfl_down_sync(0xffffffffu, t3,  o);
            t4  += __shfl_down_sync(0xffffffffu, t4,  o);
            t5  += __shfl_down_sync(0xffffffffu, t5,  o);
            t6  += __shfl_down_sync(0xffffffffu, t6,  o);
            t7  += __shfl_down_sync(0xffffffffu, t7,  o);
            t12 += __shfl_down_sync(0xffffffffu, t12, o);
        }
        if (lane == 0) {
            float A = bc[2], B = bc[3], Sx = bc[4], Sx2 = bc[5];
            float sxe   = 0.5f  * A * t12;
            float sx2e  = 0.5f  * A * (t3 + t4);
            float sx2e2 = 0.25f * A * A * (t5 + t6 + 2.f * t7);
            float Ssim  = sxe + B * Sx;
            float Ssim2 = sx2e2 + 2.f * B * sx2e + B * B * Sx2;
            float mean  = Ssim * (1.0f / (float)HW);
            float var   = (Ssim2 - Ssim * Ssim * (1.0f / (float)HW)) * (1.0f / (float)(HW - 1));
            float sd    = sqrtf(fmaxf(var, 0.f)) + 1e-5f;
            float k1    = wgt[g] / sd;
            bc[0] = 0.5f * A * k1;          // LUT scale
            bc[1] = B * k1;                 // folded into G
            bc[2] = bias[g] - mean * k1;    // c0
        }
    }
    __syncthreads();

    // fold constants into LUTs: G = 0.5*A*k1*g + B*k1 ; H = 0.5*A*k1*h
    {
        float sA = bc[0], Bk = bc[1];
        if (tid < HH)               glut[tid] = fmaf(glut[tid], sA, Bk);
        else if (tid < HH + WW)     hlut[tid - HH] *= sA;
    }
    __syncthreads();

    // ================= Pass 2: gated output (x re-read hits L2) ===============
    {
        float c0 = bc[2];
        float4 Hc = *(const float4*)&hlut[4 * csub];   // cols fixed per thread
        #pragma unroll
        for (int grp = 0; grp < NGRP; ++grp) {
            float4 v[GRP];
            float  gr[GRP];
            #pragma unroll
            for (int j = 0; j < GRP; ++j) {
                int it = grp * GRP + j;
                v[j]  = x4[it * NT + tid];
                gr[j] = glut[16 * it + rsub];
            }
            #pragma unroll
            for (int j = 0; j < GRP; ++j) {
                float4 t = v[j];
                float t0  = fmaf(t.x, gr[j] + Hc.x, c0);
                float t1  = fmaf(t.y, gr[j] + Hc.y, c0);
                float t2  = fmaf(t.z, gr[j] + Hc.z, c0);
                float t3v = fmaf(t.w, gr[j] + Hc.w, c0);
                float4 o;
                o.x = __fdividef(t.x, 1.f + __expf(-t0));
                o.y = __fdividef(t.y, 1.f + __expf(-t1));
                o.z = __fdividef(t.z, 1.f + __expf(-t2));
                o.w = __fdividef(t.w, 1.f + __expf(-t3v));
                __stcs(&o4[(grp * GRP + j) * NT + tid], o);  // stream the output
            }
        }
    }
}

extern "C" void kernel_launch(void* const* d_in, const int* in_sizes, int n_in,
                              void* d_out, int out_size)
{
    const float* x     = (const float*)d_in[0];
    const float* wgt   = (const float*)d_in[1];
    const float* bias  = (const float*)d_in[2];
    const float* one   = (const float*)d_in[3];
    const float* zero  = (const float*)d_in[4];
    const float* theta = (const float*)d_in[5];
    const float* scale = (const float*)d_in[6];
    float* out = (float*)d_out;

    cudaFuncSetAttribute(prm_kernel, cudaFuncAttributeMaxDynamicSharedMemorySize, MBYTES);
    prm_kernel<<<BSZ * GR, NT, MBYTES>>>(x, wgt, bias, one, zero, theta, scale, out);
}